// round 1
// baseline (speedup 1.0000x reference)
#include <cuda_runtime.h>
#include <math.h>

#define BATCH 2
#define SEQ   2048
#define DM    2048
#define NH    16
#define HD    128
#define NKV   4
#define KVD   512
#define QKV_N 3072
#define ROWS  (BATCH * SEQ)   // 4096

// Scratch (allocation-guard-safe __device__ globals)
__device__ float g_qkv[ROWS * QKV_N];   // [4096, 3072]
__device__ float g_att[ROWS * DM];      // [4096, 2048]

// ---------------------------------------------------------------------------
// GEMM: C[M,N] = A[M,K] @ B[K,N], row-major. M%128==0, N%128==0, K%16==0.
// 256 threads, 128x128 tile, 16-deep K slices, 8x8 register blocking.
// ---------------------------------------------------------------------------
__global__ __launch_bounds__(256) void gemm_kernel(
    const float* __restrict__ A, const float* __restrict__ B,
    float* __restrict__ C, int M, int N, int K)
{
    __shared__ float As[16][128];   // transposed: As[k][m]
    __shared__ float Bs[16][132];   // Bs[k][n], padded

    const int tid = threadIdx.x;
    const int ty = tid >> 4, tx = tid & 15;
    const int m0 = blockIdx.y * 128;
    const int n0 = blockIdx.x * 128;

    float c[8][8];
#pragma unroll
    for (int i = 0; i < 8; i++)
#pragma unroll
        for (int j = 0; j < 8; j++) c[i][j] = 0.f;

    for (int k0 = 0; k0 < K; k0 += 16) {
#pragma unroll
        for (int i = 0; i < 2; i++) {
            int e = tid + i * 256;                 // 0..511
            // A tile: 128 rows x 16 cols = 512 float4
            int ra = e >> 2, ca = e & 3;
            float4 va = *(const float4*)&A[(size_t)(m0 + ra) * K + k0 + ca * 4];
            As[ca * 4 + 0][ra] = va.x;
            As[ca * 4 + 1][ra] = va.y;
            As[ca * 4 + 2][ra] = va.z;
            As[ca * 4 + 3][ra] = va.w;
            // B tile: 16 rows x 128 cols = 512 float4
            int rb = e >> 5, cb = e & 31;
            *(float4*)&Bs[rb][cb * 4] =
                *(const float4*)&B[(size_t)(k0 + rb) * N + n0 + cb * 4];
        }
        __syncthreads();

#pragma unroll
        for (int kk = 0; kk < 16; kk++) {
            float a[8], b[8];
            float4 a0 = *(const float4*)&As[kk][ty * 8];
            float4 a1 = *(const float4*)&As[kk][ty * 8 + 4];
            a[0]=a0.x; a[1]=a0.y; a[2]=a0.z; a[3]=a0.w;
            a[4]=a1.x; a[5]=a1.y; a[6]=a1.z; a[7]=a1.w;
            float4 b0 = *(const float4*)&Bs[kk][tx * 8];
            float4 b1 = *(const float4*)&Bs[kk][tx * 8 + 4];
            b[0]=b0.x; b[1]=b0.y; b[2]=b0.z; b[3]=b0.w;
            b[4]=b1.x; b[5]=b1.y; b[6]=b1.z; b[7]=b1.w;
#pragma unroll
            for (int i = 0; i < 8; i++)
#pragma unroll
                for (int j = 0; j < 8; j++)
                    c[i][j] = fmaf(a[i], b[j], c[i][j]);
        }
        __syncthreads();
    }

#pragma unroll
    for (int i = 0; i < 8; i++) {
        float4 w0 = make_float4(c[i][0], c[i][1], c[i][2], c[i][3]);
        float4 w1 = make_float4(c[i][4], c[i][5], c[i][6], c[i][7]);
        size_t base = (size_t)(m0 + ty * 8 + i) * N + n0 + tx * 8;
        *(float4*)&C[base] = w0;
        *(float4*)&C[base + 4] = w1;
    }
}

// ---------------------------------------------------------------------------
// RoPE applied in place to q (16 heads) and k (4 heads) parts of g_qkv.
// One block per row (b*t), 256 threads; 20 heads * 64 pairs = 1280 pairs.
// ---------------------------------------------------------------------------
__global__ __launch_bounds__(256) void rope_kernel(
    float* __restrict__ qkv, const float* __restrict__ sinp,
    const float* __restrict__ cosp)
{
    const int row = blockIdx.x;       // 0..4095
    const int t = row & (SEQ - 1);
    const size_t rbase = (size_t)row * QKV_N;
#pragma unroll
    for (int i = 0; i < 5; i++) {
        int p = threadIdx.x + i * 256;    // 0..1279
        int hh = p >> 6;                  // head 0..19 (16 q + 4 k)
        int d = p & 63;
        size_t base = rbase + hh * HD;
        float x1 = qkv[base + d];
        float x2 = qkv[base + 64 + d];
        float cv = cosp[t * 64 + d];
        float sv = sinp[t * 64 + d];
        qkv[base + d]      = x1 * cv - x2 * sv;
        qkv[base + 64 + d] = x2 * cv + x1 * sv;
    }
}

// ---------------------------------------------------------------------------
// Flash attention: one block per (b, head, 64-query tile). 256 threads.
// Online softmax, O accumulators in registers (4x8 per thread).
// Smem: Q[64][132], K^T[128][68] / V[64][132] (union), S/P[64][65], stats.
// ---------------------------------------------------------------------------
#define QS_F   (64 * 132)
#define KV_F   (128 * 68)         // >= 64*132
#define S_F    (64 * 65)
#define ATTN_SMEM_FLOATS (QS_F + KV_F + S_F + 3 * 64 + 128)
#define ATTN_SMEM_BYTES  (ATTN_SMEM_FLOATS * 4)

__global__ __launch_bounds__(256) void attn_kernel(
    const float* __restrict__ qkv, const int* __restrict__ doc_ids,
    float* __restrict__ att)
{
    extern __shared__ float sm[];
    float* Qs   = sm;                  // [64][132]
    float* KVu  = Qs + QS_F;           // K^T [128][68]  or  V [64][132]
    float* S    = KVu + KV_F;          // [64][65]
    float* m_s  = S + S_F;             // [64]
    float* l_s  = m_s + 64;
    float* corr_s = l_s + 64;
    int*   qdoc = (int*)(corr_s + 64); // [64]
    int*   kdoc = qdoc + 64;           // [64]

    const int qt = blockIdx.x;         // 0..31
    const int h  = blockIdx.y;         // 0..15
    const int b  = blockIdx.z;         // 0..1
    const int g  = h >> 2;             // kv head
    const int tid = threadIdx.x;
    const int ty = tid >> 4, tx = tid & 15;
    const float scale = 0.08838834764831845f;  // 1/sqrt(128)

    const int qrow0 = qt * 64;

    // Load Q tile (scaled)
#pragma unroll
    for (int i = 0; i < 8; i++) {
        int e = tid + i * 256;          // 2048 float4
        int r = e >> 5, cc = e & 31;
        float4 v = *(const float4*)&qkv[(size_t)(b * SEQ + qrow0 + r) * QKV_N + h * HD + cc * 4];
        v.x *= scale; v.y *= scale; v.z *= scale; v.w *= scale;
        *(float4*)&Qs[r * 132 + cc * 4] = v;
    }
    if (tid < 64) {
        qdoc[tid] = doc_ids[b * SEQ + qrow0 + tid];
        m_s[tid] = -1e30f;
        l_s[tid] = 0.f;
    }
    const int qdoc_min = doc_ids[b * SEQ + qrow0];

    float co[4][8];
#pragma unroll
    for (int i = 0; i < 4; i++)
#pragma unroll
        for (int j = 0; j < 8; j++) co[i][j] = 0.f;

    __syncthreads();

    for (int kt = 0; kt <= qt; kt++) {
        const int kr0 = kt * 64;
        // doc skip: sorted doc ids -> if the newest key's doc is older than the
        // oldest query's doc, every pair in this tile is masked.
        if (doc_ids[b * SEQ + kr0 + 63] < qdoc_min) continue;

        // Load K tile transposed: KVu[d][j] = K[kr0+j][d]
#pragma unroll
        for (int i = 0; i < 8; i++) {
            int e = tid + i * 256;
            int r = e >> 5, cc = e & 31;   // r = key row, cc = d/4
            float4 v = *(const float4*)&qkv[(size_t)(b * SEQ + kr0 + r) * QKV_N + DM + g * HD + cc * 4];
            KVu[(cc * 4 + 0) * 68 + r] = v.x;
            KVu[(cc * 4 + 1) * 68 + r] = v.y;
            KVu[(cc * 4 + 2) * 68 + r] = v.z;
            KVu[(cc * 4 + 3) * 68 + r] = v.w;
        }
        if (tid < 64) kdoc[tid] = doc_ids[b * SEQ + kr0 + tid];
        __syncthreads();

        // S = Q @ K^T (4x4 per thread)
        {
            float acc[4][4];
#pragma unroll
            for (int i = 0; i < 4; i++)
#pragma unroll
                for (int j = 0; j < 4; j++) acc[i][j] = 0.f;

            for (int d = 0; d < 128; d += 4) {
                float av[4][4], bv[4][4];
#pragma unroll
                for (int ii = 0; ii < 4; ii++) {
                    float4 t4 = *(const float4*)&Qs[(ty * 4 + ii) * 132 + d];
                    av[ii][0]=t4.x; av[ii][1]=t4.y; av[ii][2]=t4.z; av[ii][3]=t4.w;
                }
#pragma unroll
                for (int u = 0; u < 4; u++) {
                    float4 t4 = *(const float4*)&KVu[(d + u) * 68 + tx * 4];
                    bv[u][0]=t4.x; bv[u][1]=t4.y; bv[u][2]=t4.z; bv[u][3]=t4.w;
                }
#pragma unroll
                for (int ii = 0; ii < 4; ii++)
#pragma unroll
                    for (int u = 0; u < 4; u++)
#pragma unroll
                        for (int jj = 0; jj < 4; jj++)
                            acc[ii][jj] = fmaf(av[ii][u], bv[u][jj], acc[ii][jj]);
            }
            // mask + store
#pragma unroll
            for (int ii = 0; ii < 4; ii++) {
                int qi = qrow0 + ty * 4 + ii;
                int qd = qdoc[ty * 4 + ii];
#pragma unroll
                for (int jj = 0; jj < 4; jj++) {
                    int kj = kr0 + tx * 4 + jj;
                    bool ok = (kj <= qi) && (qd == kdoc[tx * 4 + jj]);
                    S[(ty * 4 + ii) * 65 + tx * 4 + jj] = ok ? acc[ii][jj] : -1e30f;
                }
            }
        }
        __syncthreads();

        // Online softmax: 4 threads per row, 16 cols each.
        {
            int r = tid >> 2, q = tid & 3;
            float* Srow = &S[r * 65 + q * 16];
            float mx = -1e30f;
#pragma unroll
            for (int cc = 0; cc < 16; cc++) mx = fmaxf(mx, Srow[cc]);
            mx = fmaxf(mx, __shfl_xor_sync(0xffffffffu, mx, 1));
            mx = fmaxf(mx, __shfl_xor_sync(0xffffffffu, mx, 2));
            float m_old = m_s[r];
            float m_new = fmaxf(m_old, mx);
            float sum = 0.f;
#pragma unroll
            for (int cc = 0; cc < 16; cc++) {
                float p = __expf(Srow[cc] - m_new);
                Srow[cc] = p;
                sum += p;
            }
            sum += __shfl_xor_sync(0xffffffffu, sum, 1);
            sum += __shfl_xor_sync(0xffffffffu, sum, 2);
            if (q == 0) {
                float corr = __expf(m_old - m_new);
                corr_s[r] = corr;
                l_s[r] = l_s[r] * corr + sum;
                m_s[r] = m_new;
            }
        }

        // Load V tile row-major into the K/V union buffer (S no longer reads K)
#pragma unroll
        for (int i = 0; i < 8; i++) {
            int e = tid + i * 256;
            int r = e >> 5, cc = e & 31;
            float4 v = *(const float4*)&qkv[(size_t)(b * SEQ + kr0 + r) * QKV_N + DM + KVD + g * HD + cc * 4];
            *(float4*)&KVu[r * 132 + cc * 4] = v;
        }
        __syncthreads();

        // O = O*corr + P @ V  (4 rows x 8 cols per thread)
        {
            float corr[4];
#pragma unroll
            for (int ii = 0; ii < 4; ii++) corr[ii] = corr_s[ty * 4 + ii];
#pragma unroll
            for (int ii = 0; ii < 4; ii++)
#pragma unroll
                for (int jj = 0; jj < 8; jj++) co[ii][jj] *= corr[ii];

            for (int k = 0; k < 64; k++) {
                float p[4];
#pragma unroll
                for (int ii = 0; ii < 4; ii++) p[ii] = S[(ty * 4 + ii) * 65 + k];
                float4 v0 = *(const float4*)&KVu[k * 132 + tx * 8];
                float4 v1 = *(const float4*)&KVu[k * 132 + tx * 8 + 4];
                float vv[8] = {v0.x, v0.y, v0.z, v0.w, v1.x, v1.y, v1.z, v1.w};
#pragma unroll
                for (int ii = 0; ii < 4; ii++)
#pragma unroll
                    for (int jj = 0; jj < 8; jj++)
                        co[ii][jj] = fmaf(p[ii], vv[jj], co[ii][jj]);
            }
        }
        __syncthreads();   // before next tile overwrites KVu / S / kdoc
    }

    // Epilogue: divide by l, write out
#pragma unroll
    for (int ii = 0; ii < 4; ii++) {
        float linv = 1.f / l_s[ty * 4 + ii];
        int qi = qrow0 + ty * 4 + ii;
        size_t base = (size_t)(b * SEQ + qi) * DM + h * HD + tx * 8;
        float4 w0 = make_float4(co[ii][0]*linv, co[ii][1]*linv, co[ii][2]*linv, co[ii][3]*linv);
        float4 w1 = make_float4(co[ii][4]*linv, co[ii][5]*linv, co[ii][6]*linv, co[ii][7]*linv);
        *(float4*)&att[base] = w0;
        *(float4*)&att[base + 4] = w1;
    }
}

// ---------------------------------------------------------------------------
extern "C" void kernel_launch(void* const* d_in, const int* in_sizes, int n_in,
                              void* d_out, int out_size)
{
    const float* x    = (const float*)d_in[0];   // [2, 2048, 2048]
    const float* sinp = (const float*)d_in[1];   // [2048, 64]
    const float* cosp = (const float*)d_in[2];   // [2048, 64]
    const int*   doc  = (const int*)d_in[3];     // [2, 2048]
    const float* Wqkv = (const float*)d_in[4];   // [2048, 3072]
    const float* Wo   = (const float*)d_in[5];   // [2048, 2048]
    float* out = (float*)d_out;                  // [2, 2048, 2048]

    float* qkv = nullptr; cudaGetSymbolAddress((void**)&qkv, g_qkv);
    float* att = nullptr; cudaGetSymbolAddress((void**)&att, g_att);

    cudaFuncSetAttribute(attn_kernel,
                         cudaFuncAttributeMaxDynamicSharedMemorySize,
                         ATTN_SMEM_BYTES);

    dim3 g1(QKV_N / 128, ROWS / 128);
    gemm_kernel<<<g1, 256>>>(x, Wqkv, qkv, ROWS, QKV_N, DM);

    rope_kernel<<<ROWS, 256>>>(qkv, sinp, cosp);

    dim3 ga(SEQ / 64, NH, BATCH);
    attn_kernel<<<ga, 256, ATTN_SMEM_BYTES>>>(qkv, doc, att);

    dim3 g2(DM / 128, ROWS / 128);
    gemm_kernel<<<g2, 256>>>(att, Wo, out, ROWS, DM, DM);
}

// round 2
// speedup vs baseline: 2.1551x; 2.1551x over previous
#include <cuda_runtime.h>
#include <math.h>
#include <stdint.h>

#define BATCH 2
#define SEQ   2048
#define DM    2048
#define NH    16
#define HD    128
#define KVD   512
#define QKV_N 3072
#define ROWS  (BATCH * SEQ)   // 4096

// Scratch (allocation-guard-safe __device__ globals)
__device__ float g_qkv[ROWS * QKV_N];    // 48 MB
__device__ float g_att[ROWS * DM];       // 32 MB (tf32-rounded attention out)
__device__ float g_xr[ROWS * DM];        // 32 MB (tf32-rounded x)
__device__ float g_wqkv[DM * QKV_N];     // 24 MB (tf32-rounded W_qkv)
__device__ float g_wo[DM * DM];          // 16 MB (tf32-rounded W_o)

// ---------------------------------------------------------------------------
// tf32 RNA rounding helpers
// ---------------------------------------------------------------------------
__device__ __forceinline__ float tf32r(float x) {
    uint32_t r;
    asm("cvt.rna.tf32.f32 %0, %1;" : "=r"(r) : "f"(x));
    return __uint_as_float(r);
}

__global__ __launch_bounds__(256) void round_tf32_kernel(
    const float4* __restrict__ src, float4* __restrict__ dst, int n4)
{
    int i = blockIdx.x * blockDim.x + threadIdx.x;
    if (i < n4) {
        float4 v = src[i];
        v.x = tf32r(v.x); v.y = tf32r(v.y); v.z = tf32r(v.z); v.w = tf32r(v.w);
        dst[i] = v;
    }
}

// ---------------------------------------------------------------------------
// Tensor-core GEMM (tf32 mma.sync.m16n8k8): C[M,N] = A[M,K] @ B[K,N], row-major.
// A,B must be pre-rounded to tf32. 128x128x32 tiles, 2-stage cp.async pipeline,
// 256 threads = 8 warps in 2x4 grid, warp tile 64x32.
// ---------------------------------------------------------------------------
#define BM 128
#define BN 128
#define BK 32
#define LDA 36     // pad: bank-conflict-free A frag loads
#define LDB 136    // pad: bank-conflict-free B frag loads
#define SMEM_A_F (BM * LDA)            // 4608 floats
#define SMEM_B_F (BK * LDB)            // 4352 floats
#define GEMM_SMEM_BYTES ((SMEM_A_F + SMEM_B_F) * 2 * 4)   // 71680 B

__device__ __forceinline__ void cp_async16(uint32_t dst, const void* src) {
    asm volatile("cp.async.cg.shared.global [%0], [%1], 16;\n" :: "r"(dst), "l"(src));
}

__global__ __launch_bounds__(256) void gemm_tc(
    const float* __restrict__ A, const float* __restrict__ B,
    float* __restrict__ C, int M, int N, int K)
{
    extern __shared__ float sm[];
    float* sA = sm;                       // [2][BM*LDA]
    float* sB = sm + 2 * SMEM_A_F;        // [2][BK*LDB]

    const int tid  = threadIdx.x;
    const int warp = tid >> 5;
    const int lane = tid & 31;
    const int wm = (warp >> 2) * 64;      // warp row offset in tile
    const int wn = (warp & 3) * 32;       // warp col offset in tile
    const int gID = lane >> 2;            // 0..7
    const int tg  = lane & 3;             // 0..3

    const int m0 = blockIdx.y * BM;
    const int n0 = blockIdx.x * BN;

    float c[4][4][4];
#pragma unroll
    for (int a = 0; a < 4; a++)
#pragma unroll
        for (int b = 0; b < 4; b++)
#pragma unroll
            for (int d = 0; d < 4; d++) c[a][b][d] = 0.f;

    const uint32_t sA_u = (uint32_t)__cvta_generic_to_shared(sA);
    const uint32_t sB_u = (uint32_t)__cvta_generic_to_shared(sB);

    const int NK = K / BK;

#define LOAD_STAGE(s, k0)                                                     \
    do {                                                                      \
        _Pragma("unroll")                                                     \
        for (int i = 0; i < 4; i++) {                                         \
            int e = tid + i * 256;                                            \
            int ra = e >> 3, ca = e & 7;                                      \
            cp_async16(sA_u + ((s) * SMEM_A_F + ra * LDA + ca * 4) * 4,       \
                       A + (size_t)(m0 + ra) * K + (k0) + ca * 4);            \
        }                                                                     \
        _Pragma("unroll")                                                     \
        for (int i = 0; i < 4; i++) {                                         \
            int e = tid + i * 256;                                            \
            int rb = e >> 5, cb = e & 31;                                     \
            cp_async16(sB_u + ((s) * SMEM_B_F + rb * LDB + cb * 4) * 4,       \
                       B + (size_t)((k0) + rb) * N + n0 + cb * 4);            \
        }                                                                     \
    } while (0)

    LOAD_STAGE(0, 0);
    asm volatile("cp.async.commit_group;\n");

    for (int kt = 0; kt < NK; kt++) {
        if (kt + 1 < NK) LOAD_STAGE((kt + 1) & 1, (kt + 1) * BK);
        asm volatile("cp.async.commit_group;\n");
        asm volatile("cp.async.wait_group 1;\n");
        __syncthreads();

        const uint32_t* As = (const uint32_t*)(sA + (kt & 1) * SMEM_A_F);
        const uint32_t* Bs = (const uint32_t*)(sB + (kt & 1) * SMEM_B_F);

#pragma unroll
        for (int kk = 0; kk < BK; kk += 8) {
            uint32_t af[4][4], bf[4][2];
#pragma unroll
            for (int mi = 0; mi < 4; mi++) {
                int r = wm + mi * 16 + gID;
                af[mi][0] = As[r * LDA + kk + tg];
                af[mi][1] = As[(r + 8) * LDA + kk + tg];
                af[mi][2] = As[r * LDA + kk + tg + 4];
                af[mi][3] = As[(r + 8) * LDA + kk + tg + 4];
            }
#pragma unroll
            for (int ni = 0; ni < 4; ni++) {
                int cc = wn + ni * 8 + gID;
                bf[ni][0] = Bs[(kk + tg) * LDB + cc];
                bf[ni][1] = Bs[(kk + tg + 4) * LDB + cc];
            }
#pragma unroll
            for (int mi = 0; mi < 4; mi++)
#pragma unroll
                for (int ni = 0; ni < 4; ni++)
                    asm volatile(
                        "mma.sync.aligned.m16n8k8.row.col.f32.tf32.tf32.f32 "
                        "{%0,%1,%2,%3}, {%4,%5,%6,%7}, {%8,%9}, {%0,%1,%2,%3};\n"
                        : "+f"(c[mi][ni][0]), "+f"(c[mi][ni][1]),
                          "+f"(c[mi][ni][2]), "+f"(c[mi][ni][3])
                        : "r"(af[mi][0]), "r"(af[mi][1]),
                          "r"(af[mi][2]), "r"(af[mi][3]),
                          "r"(bf[ni][0]), "r"(bf[ni][1]));
        }
        __syncthreads();
    }

#pragma unroll
    for (int mi = 0; mi < 4; mi++) {
#pragma unroll
        for (int ni = 0; ni < 4; ni++) {
            int r  = m0 + wm + mi * 16 + gID;
            int cc = n0 + wn + ni * 8 + tg * 2;
            *(float2*)&C[(size_t)r * N + cc] =
                make_float2(c[mi][ni][0], c[mi][ni][1]);
            *(float2*)&C[(size_t)(r + 8) * N + cc] =
                make_float2(c[mi][ni][2], c[mi][ni][3]);
        }
    }
#undef LOAD_STAGE
}

// ---------------------------------------------------------------------------
// RoPE in place on q (16 heads) + k (4 heads) of g_qkv.
// ---------------------------------------------------------------------------
__global__ __launch_bounds__(256) void rope_kernel(
    float* __restrict__ qkv, const float* __restrict__ sinp,
    const float* __restrict__ cosp)
{
    const int row = blockIdx.x;
    const int t = row & (SEQ - 1);
    const size_t rbase = (size_t)row * QKV_N;
#pragma unroll
    for (int i = 0; i < 5; i++) {
        int p = threadIdx.x + i * 256;    // 0..1279
        int hh = p >> 6;
        int d = p & 63;
        size_t base = rbase + hh * HD;
        float x1 = qkv[base + d];
        float x2 = qkv[base + 64 + d];
        float cv = cosp[t * 64 + d];
        float sv = sinp[t * 64 + d];
        qkv[base + d]      = x1 * cv - x2 * sv;
        qkv[base + 64 + d] = x2 * cv + x1 * sv;
    }
}

// ---------------------------------------------------------------------------
// Flash attention (fp32 FMA, unchanged except tf32-rounded epilogue so the
// output GEMM can consume it directly as a tf32 operand).
// ---------------------------------------------------------------------------
#define QS_F   (64 * 132)
#define KV_F   (128 * 68)
#define S_F    (64 * 65)
#define ATTN_SMEM_FLOATS (QS_F + KV_F + S_F + 3 * 64 + 128)
#define ATTN_SMEM_BYTES  (ATTN_SMEM_FLOATS * 4)

__global__ __launch_bounds__(256) void attn_kernel(
    const float* __restrict__ qkv, const int* __restrict__ doc_ids,
    float* __restrict__ att)
{
    extern __shared__ float sm[];
    float* Qs   = sm;
    float* KVu  = Qs + QS_F;
    float* S    = KVu + KV_F;
    float* m_s  = S + S_F;
    float* l_s  = m_s + 64;
    float* corr_s = l_s + 64;
    int*   qdoc = (int*)(corr_s + 64);
    int*   kdoc = qdoc + 64;

    const int qt = blockIdx.x;
    const int h  = blockIdx.y;
    const int b  = blockIdx.z;
    const int g  = h >> 2;
    const int tid = threadIdx.x;
    const int ty = tid >> 4, tx = tid & 15;
    const float scale = 0.08838834764831845f;

    const int qrow0 = qt * 64;

#pragma unroll
    for (int i = 0; i < 8; i++) {
        int e = tid + i * 256;
        int r = e >> 5, cc = e & 31;
        float4 v = *(const float4*)&qkv[(size_t)(b * SEQ + qrow0 + r) * QKV_N + h * HD + cc * 4];
        v.x *= scale; v.y *= scale; v.z *= scale; v.w *= scale;
        *(float4*)&Qs[r * 132 + cc * 4] = v;
    }
    if (tid < 64) {
        qdoc[tid] = doc_ids[b * SEQ + qrow0 + tid];
        m_s[tid] = -1e30f;
        l_s[tid] = 0.f;
    }
    const int qdoc_min = doc_ids[b * SEQ + qrow0];

    float co[4][8];
#pragma unroll
    for (int i = 0; i < 4; i++)
#pragma unroll
        for (int j = 0; j < 8; j++) co[i][j] = 0.f;

    __syncthreads();

    for (int kt = 0; kt <= qt; kt++) {
        const int kr0 = kt * 64;
        if (doc_ids[b * SEQ + kr0 + 63] < qdoc_min) continue;

#pragma unroll
        for (int i = 0; i < 8; i++) {
            int e = tid + i * 256;
            int r = e >> 5, cc = e & 31;
            float4 v = *(const float4*)&qkv[(size_t)(b * SEQ + kr0 + r) * QKV_N + DM + g * HD + cc * 4];
            KVu[(cc * 4 + 0) * 68 + r] = v.x;
            KVu[(cc * 4 + 1) * 68 + r] = v.y;
            KVu[(cc * 4 + 2) * 68 + r] = v.z;
            KVu[(cc * 4 + 3) * 68 + r] = v.w;
        }
        if (tid < 64) kdoc[tid] = doc_ids[b * SEQ + kr0 + tid];
        __syncthreads();

        {
            float acc[4][4];
#pragma unroll
            for (int i = 0; i < 4; i++)
#pragma unroll
                for (int j = 0; j < 4; j++) acc[i][j] = 0.f;

            for (int d = 0; d < 128; d += 4) {
                float av[4][4], bv[4][4];
#pragma unroll
                for (int ii = 0; ii < 4; ii++) {
                    float4 t4 = *(const float4*)&Qs[(ty * 4 + ii) * 132 + d];
                    av[ii][0]=t4.x; av[ii][1]=t4.y; av[ii][2]=t4.z; av[ii][3]=t4.w;
                }
#pragma unroll
                for (int u = 0; u < 4; u++) {
                    float4 t4 = *(const float4*)&KVu[(d + u) * 68 + tx * 4];
                    bv[u][0]=t4.x; bv[u][1]=t4.y; bv[u][2]=t4.z; bv[u][3]=t4.w;
                }
#pragma unroll
                for (int ii = 0; ii < 4; ii++)
#pragma unroll
                    for (int u = 0; u < 4; u++)
#pragma unroll
                        for (int jj = 0; jj < 4; jj++)
                            acc[ii][jj] = fmaf(av[ii][u], bv[u][jj], acc[ii][jj]);
            }
#pragma unroll
            for (int ii = 0; ii < 4; ii++) {
                int qi = qrow0 + ty * 4 + ii;
                int qd = qdoc[ty * 4 + ii];
#pragma unroll
                for (int jj = 0; jj < 4; jj++) {
                    int kj = kr0 + tx * 4 + jj;
                    bool ok = (kj <= qi) && (qd == kdoc[tx * 4 + jj]);
                    S[(ty * 4 + ii) * 65 + tx * 4 + jj] = ok ? acc[ii][jj] : -1e30f;
                }
            }
        }
        __syncthreads();

        {
            int r = tid >> 2, q = tid & 3;
            float* Srow = &S[r * 65 + q * 16];
            float mx = -1e30f;
#pragma unroll
            for (int cc = 0; cc < 16; cc++) mx = fmaxf(mx, Srow[cc]);
            mx = fmaxf(mx, __shfl_xor_sync(0xffffffffu, mx, 1));
            mx = fmaxf(mx, __shfl_xor_sync(0xffffffffu, mx, 2));
            float m_old = m_s[r];
            float m_new = fmaxf(m_old, mx);
            float sum = 0.f;
#pragma unroll
            for (int cc = 0; cc < 16; cc++) {
                float p = __expf(Srow[cc] - m_new);
                Srow[cc] = p;
                sum += p;
            }
            sum += __shfl_xor_sync(0xffffffffu, sum, 1);
            sum += __shfl_xor_sync(0xffffffffu, sum, 2);
            if (q == 0) {
                float corr = __expf(m_old - m_new);
                corr_s[r] = corr;
                l_s[r] = l_s[r] * corr + sum;
                m_s[r] = m_new;
            }
        }

#pragma unroll
        for (int i = 0; i < 8; i++) {
            int e = tid + i * 256;
            int r = e >> 5, cc = e & 31;
            float4 v = *(const float4*)&qkv[(size_t)(b * SEQ + kr0 + r) * QKV_N + DM + KVD + g * HD + cc * 4];
            *(float4*)&KVu[r * 132 + cc * 4] = v;
        }
        __syncthreads();

        {
            float corr[4];
#pragma unroll
            for (int ii = 0; ii < 4; ii++) corr[ii] = corr_s[ty * 4 + ii];
#pragma unroll
            for (int ii = 0; ii < 4; ii++)
#pragma unroll
                for (int jj = 0; jj < 8; jj++) co[ii][jj] *= corr[ii];

            for (int k = 0; k < 64; k++) {
                float p[4];
#pragma unroll
                for (int ii = 0; ii < 4; ii++) p[ii] = S[(ty * 4 + ii) * 65 + k];
                float4 v0 = *(const float4*)&KVu[k * 132 + tx * 8];
                float4 v1 = *(const float4*)&KVu[k * 132 + tx * 8 + 4];
                float vv[8] = {v0.x, v0.y, v0.z, v0.w, v1.x, v1.y, v1.z, v1.w};
#pragma unroll
                for (int ii = 0; ii < 4; ii++)
#pragma unroll
                    for (int jj = 0; jj < 8; jj++)
                        co[ii][jj] = fmaf(p[ii], vv[jj], co[ii][jj]);
            }
        }
        __syncthreads();
    }

#pragma unroll
    for (int ii = 0; ii < 4; ii++) {
        float linv = 1.f / l_s[ty * 4 + ii];
        int qi = qrow0 + ty * 4 + ii;
        size_t base = (size_t)(b * SEQ + qi) * DM + h * HD + tx * 8;
        float4 w0 = make_float4(tf32r(co[ii][0]*linv), tf32r(co[ii][1]*linv),
                                tf32r(co[ii][2]*linv), tf32r(co[ii][3]*linv));
        float4 w1 = make_float4(tf32r(co[ii][4]*linv), tf32r(co[ii][5]*linv),
                                tf32r(co[ii][6]*linv), tf32r(co[ii][7]*linv));
        *(float4*)&att[base] = w0;
        *(float4*)&att[base + 4] = w1;
    }
}

// ---------------------------------------------------------------------------
extern "C" void kernel_launch(void* const* d_in, const int* in_sizes, int n_in,
                              void* d_out, int out_size)
{
    const float* x    = (const float*)d_in[0];
    const float* sinp = (const float*)d_in[1];
    const float* cosp = (const float*)d_in[2];
    const int*   doc  = (const int*)d_in[3];
    const float* Wqkv = (const float*)d_in[4];
    const float* Wo   = (const float*)d_in[5];
    float* out = (float*)d_out;

    float* qkv = nullptr;  cudaGetSymbolAddress((void**)&qkv, g_qkv);
    float* att = nullptr;  cudaGetSymbolAddress((void**)&att, g_att);
    float* xr  = nullptr;  cudaGetSymbolAddress((void**)&xr,  g_xr);
    float* wq  = nullptr;  cudaGetSymbolAddress((void**)&wq,  g_wqkv);
    float* wo  = nullptr;  cudaGetSymbolAddress((void**)&wo,  g_wo);

    cudaFuncSetAttribute(attn_kernel,
                         cudaFuncAttributeMaxDynamicSharedMemorySize,
                         ATTN_SMEM_BYTES);
    cudaFuncSetAttribute(gemm_tc,
                         cudaFuncAttributeMaxDynamicSharedMemorySize,
                         GEMM_SMEM_BYTES);

    // tf32-round the GEMM operands (RNA: zero-mean rounding, ~3e-4 norm err)
    round_tf32_kernel<<<(ROWS * DM / 4) / 256, 256>>>((const float4*)x, (float4*)xr, ROWS * DM / 4);
    round_tf32_kernel<<<(DM * QKV_N / 4) / 256, 256>>>((const float4*)Wqkv, (float4*)wq, DM * QKV_N / 4);
    round_tf32_kernel<<<(DM * DM / 4) / 256, 256>>>((const float4*)Wo, (float4*)wo, DM * DM / 4);

    dim3 g1(QKV_N / BN, ROWS / BM);
    gemm_tc<<<g1, 256, GEMM_SMEM_BYTES>>>(xr, wq, qkv, ROWS, QKV_N, DM);

    rope_kernel<<<ROWS, 256>>>(qkv, sinp, cosp);

    dim3 ga(SEQ / 64, NH, BATCH);
    attn_kernel<<<ga, 256, ATTN_SMEM_BYTES>>>(qkv, doc, att);

    dim3 g2(DM / BN, ROWS / BM);
    gemm_tc<<<g2, 256, GEMM_SMEM_BYTES>>>(att, wo, out, ROWS, DM, DM);
}

// round 5
// speedup vs baseline: 3.1973x; 1.4836x over previous
#include <cuda_runtime.h>
#include <math.h>
#include <stdint.h>

#define BATCH 2
#define SEQ   2048
#define DM    2048
#define NH    16
#define HD    128
#define KVD   512
#define QKV_N 3072
#define ROWS  (BATCH * SEQ)   // 4096

// Scratch (allocation-guard-safe __device__ globals)
__device__ float g_qkv[ROWS * QKV_N];
__device__ float g_att[ROWS * DM];
__device__ float g_xr[ROWS * DM];
__device__ float g_wqkv[DM * QKV_N];
__device__ float g_wo[DM * DM];

__device__ __forceinline__ float tf32r(float x) {
    uint32_t r;
    asm("cvt.rna.tf32.f32 %0, %1;" : "=r"(r) : "f"(x));
    return __uint_as_float(r);
}

__device__ __forceinline__ void mma_tf32(float* c, const uint32_t* a,
                                         uint32_t b0, uint32_t b1) {
    asm volatile(
        "mma.sync.aligned.m16n8k8.row.col.f32.tf32.tf32.f32 "
        "{%0,%1,%2,%3}, {%4,%5,%6,%7}, {%8,%9}, {%0,%1,%2,%3};\n"
        : "+f"(c[0]), "+f"(c[1]), "+f"(c[2]), "+f"(c[3])
        : "r"(a[0]), "r"(a[1]), "r"(a[2]), "r"(a[3]), "r"(b0), "r"(b1));
}

__device__ __forceinline__ void cp_async16(uint32_t dst, const void* src) {
    asm volatile("cp.async.cg.shared.global [%0], [%1], 16;\n" :: "r"(dst), "l"(src));
}

__global__ __launch_bounds__(256) void round_tf32_kernel(
    const float4* __restrict__ src, float4* __restrict__ dst, int n4)
{
    int i = blockIdx.x * blockDim.x + threadIdx.x;
    if (i < n4) {
        float4 v = src[i];
        v.x = tf32r(v.x); v.y = tf32r(v.y); v.z = tf32r(v.z); v.w = tf32r(v.w);
        dst[i] = v;
    }
}

// ---------------------------------------------------------------------------
// tf32 tensor GEMM v2: 128x256x32 tile, 512 threads (16 warps, warp tile
// 32x64), 3-stage cp.async pipeline. C[M,N] = A[M,K] @ B[K,N] row-major.
// ---------------------------------------------------------------------------
#define BM 128
#define BN 256
#define BK 32
#define STAGES 3
#define LDA 36
#define LDB 264
#define SA_F (BM * LDA)                  // 4608
#define SB_F (BK * LDB)                  // 8448
#define STAGE_F (SA_F + SB_F)            // 13056
#define GEMM_SMEM_BYTES (STAGE_F * STAGES * 4)   // 156672

__global__ __launch_bounds__(512, 1) void gemm_tc(
    const float* __restrict__ A, const float* __restrict__ B,
    float* __restrict__ C, int M, int N, int K)
{
    extern __shared__ float sm[];

    const int tid  = threadIdx.x;
    const int warp = tid >> 5;
    const int lane = tid & 31;
    const int wm = (warp >> 2) * 32;
    const int wn = (warp & 3) * 64;
    const int gID = lane >> 2;
    const int tg  = lane & 3;

    const int m0 = blockIdx.y * BM;
    const int n0 = blockIdx.x * BN;

    float c[2][8][4];
#pragma unroll
    for (int a = 0; a < 2; a++)
#pragma unroll
        for (int b = 0; b < 8; b++)
#pragma unroll
            for (int d = 0; d < 4; d++) c[a][b][d] = 0.f;

    const uint32_t sm_u = (uint32_t)__cvta_generic_to_shared(sm);
    const int NK = K / BK;

#define G_LOAD(s, k0)                                                         \
    do {                                                                      \
        _Pragma("unroll")                                                     \
        for (int i = 0; i < 2; i++) {                                         \
            int e = tid + i * 512;                                            \
            int ra = e >> 3, ca = e & 7;                                      \
            cp_async16(sm_u + ((s) * STAGE_F + ra * LDA + ca * 4) * 4,        \
                       A + (size_t)(m0 + ra) * K + (k0) + ca * 4);            \
        }                                                                     \
        _Pragma("unroll")                                                     \
        for (int i = 0; i < 4; i++) {                                         \
            int e = tid + i * 512;                                            \
            int rb = e >> 6, cb = e & 63;                                     \
            cp_async16(sm_u + ((s) * STAGE_F + SA_F + rb * LDB + cb * 4) * 4, \
                       B + (size_t)((k0) + rb) * N + n0 + cb * 4);            \
        }                                                                     \
    } while (0)

    G_LOAD(0, 0);
    asm volatile("cp.async.commit_group;\n");
    G_LOAD(1, BK);
    asm volatile("cp.async.commit_group;\n");

    int stage = 0;
    for (int kt = 0; kt < NK; kt++) {
        asm volatile("cp.async.wait_group 1;\n");
        __syncthreads();

        if (kt + 2 < NK) {
            int ns = stage + 2; if (ns >= STAGES) ns -= STAGES;
            G_LOAD(ns, (kt + 2) * BK);
        }
        asm volatile("cp.async.commit_group;\n");

        const uint32_t* As = (const uint32_t*)(sm + stage * STAGE_F);
        const uint32_t* Bs = As + SA_F;

#pragma unroll
        for (int kk = 0; kk < BK; kk += 8) {
            uint32_t af[2][4], bf[8][2];
#pragma unroll
            for (int mi = 0; mi < 2; mi++) {
                int r = wm + mi * 16 + gID;
                af[mi][0] = As[r * LDA + kk + tg];
                af[mi][1] = As[(r + 8) * LDA + kk + tg];
                af[mi][2] = As[r * LDA + kk + tg + 4];
                af[mi][3] = As[(r + 8) * LDA + kk + tg + 4];
            }
#pragma unroll
            for (int ni = 0; ni < 8; ni++) {
                int cc = wn + ni * 8 + gID;
                bf[ni][0] = Bs[(kk + tg) * LDB + cc];
                bf[ni][1] = Bs[(kk + tg + 4) * LDB + cc];
            }
#pragma unroll
            for (int mi = 0; mi < 2; mi++)
#pragma unroll
                for (int ni = 0; ni < 8; ni++)
                    mma_tf32(c[mi][ni], af[mi], bf[ni][0], bf[ni][1]);
        }
        stage++; if (stage >= STAGES) stage = 0;
    }

#pragma unroll
    for (int mi = 0; mi < 2; mi++) {
#pragma unroll
        for (int ni = 0; ni < 8; ni++) {
            int r  = m0 + wm + mi * 16 + gID;
            int cc = n0 + wn + ni * 8 + tg * 2;
            *(float2*)&C[(size_t)r * N + cc] = make_float2(c[mi][ni][0], c[mi][ni][1]);
            *(float2*)&C[(size_t)(r + 8) * N + cc] = make_float2(c[mi][ni][2], c[mi][ni][3]);
        }
    }
#undef G_LOAD
}

// ---------------------------------------------------------------------------
// RoPE in place on q + k parts of g_qkv.
// ---------------------------------------------------------------------------
__global__ __launch_bounds__(256) void rope_kernel(
    float* __restrict__ qkv, const float* __restrict__ sinp,
    const float* __restrict__ cosp)
{
    const int row = blockIdx.x;
    const int t = row & (SEQ - 1);
    const size_t rbase = (size_t)row * QKV_N;
#pragma unroll
    for (int i = 0; i < 5; i++) {
        int p = threadIdx.x + i * 256;
        int hh = p >> 6;
        int d = p & 63;
        size_t base = rbase + hh * HD;
        float x1 = qkv[base + d];
        float x2 = qkv[base + 64 + d];
        float cv = cosp[t * 64 + d];
        float sv = sinp[t * 64 + d];
        qkv[base + d]      = x1 * cv - x2 * sv;
        qkv[base + 64 + d] = x2 * cv + x1 * sv;
    }
}

// ---------------------------------------------------------------------------
// Tensor-core flash attention (tf32 mma). Block = (128 q rows, head, batch),
// 256 threads = 8 warps; warp w owns S/O rows [16w, 16w+16). 64-key tiles.
// Softmax stats live in registers (4-thread shfl groups).
// ---------------------------------------------------------------------------
#define ATM 128
#define ATN 64
#define QP  136
#define KP  136
#define VP  136
#define PP  68
#define ATTN_SMEM_FLOATS (ATM*QP + ATN*KP + ATN*VP + ATM*PP + 64)
#define ATTN_SMEM_BYTES  (ATTN_SMEM_FLOATS * 4)

__global__ __launch_bounds__(256, 1) void attn_tc(
    const float* __restrict__ qkv, const int* __restrict__ doc_ids,
    float* __restrict__ att)
{
    extern __shared__ float sm[];
    float* Qs = sm;                       // [128][136]
    float* Ks = Qs + ATM * QP;            // [64][136]
    float* Vs = Ks + ATN * KP;            // [64][136]
    float* Ps = Vs + ATN * VP;            // [128][68]

    const int qt = gridDim.x - 1 - blockIdx.x;   // big tiles first (balance)
    const int h  = blockIdx.y;
    const int b  = blockIdx.z;
    const int g  = h >> 2;
    const int tid = threadIdx.x;
    const int warp = tid >> 5;
    const int lane = tid & 31;
    const int gID = lane >> 2;
    const int tg  = lane & 3;
    const int tg2 = tg * 2;
    const float scale = 0.08838834764831845f;

    const int qrow0 = qt * ATM;
    const int seq_base = b * SEQ;

    const uint32_t* Qu = (const uint32_t*)Qs;
    const uint32_t* Ku = (const uint32_t*)Ks;
    const uint32_t* Vu = (const uint32_t*)Vs;
    const uint32_t* Pu = (const uint32_t*)Ps;

    // Load Q tile (scale + tf32 round): 128x128 = 4096 float4
#pragma unroll
    for (int i = 0; i < 16; i++) {
        int e = tid + i * 256;
        int r = e >> 5, cc = e & 31;
        float4 v = *(const float4*)&qkv[(size_t)(seq_base + qrow0 + r) * QKV_N + h * HD + cc * 4];
        v.x = tf32r(v.x * scale); v.y = tf32r(v.y * scale);
        v.z = tf32r(v.z * scale); v.w = tf32r(v.w * scale);
        *(float4*)&Qs[r * QP + cc * 4] = v;
    }
    __syncthreads();

    const int r0 = warp * 16 + gID;        // this thread's S/O rows
    const int r1 = r0 + 8;
    const int qi0 = qrow0 + r0;
    const int qi1 = qrow0 + r1;
    const int qd0 = doc_ids[seq_base + qi0];
    const int qd1 = doc_ids[seq_base + qi1];
    const int qd_lo = doc_ids[seq_base + qrow0];
    const int qd_hi = doc_ids[seq_base + qrow0 + ATM - 1];

    float m0 = -1e30f, m1 = -1e30f, l0 = 0.f, l1 = 0.f;
    float o[16][4];
#pragma unroll
    for (int i = 0; i < 16; i++)
#pragma unroll
        for (int j = 0; j < 4; j++) o[i][j] = 0.f;

    const int nkt = 2 * qt + 2;
    for (int kt = 0; kt < nkt; kt++) {
        const int kr0 = kt * ATN;
        const int kd_lo = doc_ids[seq_base + kr0];
        const int kd_hi = doc_ids[seq_base + kr0 + ATN - 1];
        if (kd_hi < qd_lo) continue;       // whole tile doc-masked (sorted ids)

        const bool need_causal = (kr0 + ATN - 1 > qrow0);
        const bool need_doc = !(kd_lo == kd_hi && qd_lo == qd_hi && qd_lo == kd_lo);

        __syncthreads();   // prior iteration done reading Ks/Vs

        // Load K and V tiles (tf32-rounded): each 64x128 = 2048 float4
#pragma unroll
        for (int i = 0; i < 8; i++) {
            int e = tid + i * 256;
            int r = e >> 5, cc = e & 31;
            size_t rowb = (size_t)(seq_base + kr0 + r) * QKV_N + DM + g * HD + cc * 4;
            float4 kv = *(const float4*)&qkv[rowb];
            kv.x = tf32r(kv.x); kv.y = tf32r(kv.y); kv.z = tf32r(kv.z); kv.w = tf32r(kv.w);
            *(float4*)&Ks[r * KP + cc * 4] = kv;
            float4 vv = *(const float4*)&qkv[rowb + KVD];
            vv.x = tf32r(vv.x); vv.y = tf32r(vv.y); vv.z = tf32r(vv.z); vv.w = tf32r(vv.w);
            *(float4*)&Vs[r * VP + cc * 4] = vv;
        }
        __syncthreads();

        // --- S = Q @ K^T ---
        float s[8][4];
#pragma unroll
        for (int ni = 0; ni < 8; ni++)
#pragma unroll
            for (int j = 0; j < 4; j++) s[ni][j] = 0.f;

#pragma unroll
        for (int kk = 0; kk < HD; kk += 8) {
            uint32_t a[4];
            a[0] = Qu[r0 * QP + kk + tg];
            a[1] = Qu[r1 * QP + kk + tg];
            a[2] = Qu[r0 * QP + kk + tg + 4];
            a[3] = Qu[r1 * QP + kk + tg + 4];
#pragma unroll
            for (int ni = 0; ni < 8; ni++) {
                uint32_t b0 = Ku[(ni * 8 + gID) * KP + kk + tg];
                uint32_t b1 = Ku[(ni * 8 + gID) * KP + kk + tg + 4];
                mma_tf32(s[ni], a, b0, b1);
            }
        }

        // --- mask ---
        if (need_causal || need_doc) {
#pragma unroll
            for (int ni = 0; ni < 8; ni++) {
                int kj = kr0 + ni * 8 + tg2;
                int kda = doc_ids[seq_base + kj];
                int kdb = doc_ids[seq_base + kj + 1];
                if ((need_causal && kj > qi0)     || (need_doc && kda != qd0)) s[ni][0] = -1e30f;
                if ((need_causal && kj + 1 > qi0) || (need_doc && kdb != qd0)) s[ni][1] = -1e30f;
                if ((need_causal && kj > qi1)     || (need_doc && kda != qd1)) s[ni][2] = -1e30f;
                if ((need_causal && kj + 1 > qi1) || (need_doc && kdb != qd1)) s[ni][3] = -1e30f;
            }
        }

        // --- online softmax (registers; reduce across 4-thread tg group) ---
        float mx0 = -1e30f, mx1 = -1e30f;
#pragma unroll
        for (int ni = 0; ni < 8; ni++) {
            mx0 = fmaxf(mx0, fmaxf(s[ni][0], s[ni][1]));
            mx1 = fmaxf(mx1, fmaxf(s[ni][2], s[ni][3]));
        }
        mx0 = fmaxf(mx0, __shfl_xor_sync(0xffffffffu, mx0, 1));
        mx0 = fmaxf(mx0, __shfl_xor_sync(0xffffffffu, mx0, 2));
        mx1 = fmaxf(mx1, __shfl_xor_sync(0xffffffffu, mx1, 1));
        mx1 = fmaxf(mx1, __shfl_xor_sync(0xffffffffu, mx1, 2));

        float mn0 = fmaxf(m0, mx0), mn1 = fmaxf(m1, mx1);
        float corr0 = __expf(m0 - mn0), corr1 = __expf(m1 - mn1);
        float sum0 = 0.f, sum1 = 0.f;
#pragma unroll
        for (int ni = 0; ni < 8; ni++) {
            s[ni][0] = __expf(s[ni][0] - mn0);
            s[ni][1] = __expf(s[ni][1] - mn0);
            s[ni][2] = __expf(s[ni][2] - mn1);
            s[ni][3] = __expf(s[ni][3] - mn1);
            sum0 += s[ni][0] + s[ni][1];
            sum1 += s[ni][2] + s[ni][3];
        }
        sum0 += __shfl_xor_sync(0xffffffffu, sum0, 1);
        sum0 += __shfl_xor_sync(0xffffffffu, sum0, 2);
        sum1 += __shfl_xor_sync(0xffffffffu, sum1, 1);
        sum1 += __shfl_xor_sync(0xffffffffu, sum1, 2);
        l0 = l0 * corr0 + sum0;  m0 = mn0;
        l1 = l1 * corr1 + sum1;  m1 = mn1;

#pragma unroll
        for (int ni = 0; ni < 16; ni++) {
            o[ni][0] *= corr0; o[ni][1] *= corr0;
            o[ni][2] *= corr1; o[ni][3] *= corr1;
        }

        // --- store P (tf32-rounded) to smem; consumed by same warp only ---
#pragma unroll
        for (int ni = 0; ni < 8; ni++) {
            *(float2*)&Ps[r0 * PP + ni * 8 + tg2] = make_float2(tf32r(s[ni][0]), tf32r(s[ni][1]));
            *(float2*)&Ps[r1 * PP + ni * 8 + tg2] = make_float2(tf32r(s[ni][2]), tf32r(s[ni][3]));
        }
        __syncwarp();

        // --- O += P @ V ---
#pragma unroll
        for (int kk = 0; kk < ATN; kk += 8) {
            uint32_t a[4];
            a[0] = Pu[r0 * PP + kk + tg];
            a[1] = Pu[r1 * PP + kk + tg];
            a[2] = Pu[r0 * PP + kk + tg + 4];
            a[3] = Pu[r1 * PP + kk + tg + 4];
#pragma unroll
            for (int ni = 0; ni < 16; ni++) {
                uint32_t b0 = Vu[(kk + tg) * VP + ni * 8 + gID];
                uint32_t b1 = Vu[(kk + tg + 4) * VP + ni * 8 + gID];
                mma_tf32(o[ni], a, b0, b1);
            }
        }
    }

    // Epilogue: normalize, tf32-round (Wo GEMM operand), store.
    float li0 = 1.f / l0, li1 = 1.f / l1;
#pragma unroll
    for (int ni = 0; ni < 16; ni++) {
        size_t b0a = (size_t)(seq_base + qi0) * DM + h * HD + ni * 8 + tg2;
        size_t b1a = (size_t)(seq_base + qi1) * DM + h * HD + ni * 8 + tg2;
        *(float2*)&att[b0a] = make_float2(tf32r(o[ni][0] * li0), tf32r(o[ni][1] * li0));
        *(float2*)&att[b1a] = make_float2(tf32r(o[ni][2] * li1), tf32r(o[ni][3] * li1));
    }
}

// ---------------------------------------------------------------------------
extern "C" void kernel_launch(void* const* d_in, const int* in_sizes, int n_in,
                              void* d_out, int out_size)
{
    const float* x    = (const float*)d_in[0];
    const float* sinp = (const float*)d_in[1];
    const float* cosp = (const float*)d_in[2];
    const int*   doc  = (const int*)d_in[3];
    const float* Wqkv = (const float*)d_in[4];
    const float* Wo   = (const float*)d_in[5];
    float* out = (float*)d_out;

    float* qkv = nullptr;  cudaGetSymbolAddress((void**)&qkv, g_qkv);
    float* att = nullptr;  cudaGetSymbolAddress((void**)&att, g_att);
    float* xr  = nullptr;  cudaGetSymbolAddress((void**)&xr,  g_xr);
    float* wq  = nullptr;  cudaGetSymbolAddress((void**)&wq,  g_wqkv);
    float* wo  = nullptr;  cudaGetSymbolAddress((void**)&wo,  g_wo);

    cudaFuncSetAttribute(attn_tc, cudaFuncAttributeMaxDynamicSharedMemorySize,
                         ATTN_SMEM_BYTES);
    cudaFuncSetAttribute(gemm_tc, cudaFuncAttributeMaxDynamicSharedMemorySize,
                         GEMM_SMEM_BYTES);

    round_tf32_kernel<<<(ROWS * DM / 4) / 256, 256>>>((const float4*)x, (float4*)xr, ROWS * DM / 4);
    round_tf32_kernel<<<(DM * QKV_N / 4) / 256, 256>>>((const float4*)Wqkv, (float4*)wq, DM * QKV_N / 4);
    round_tf32_kernel<<<(DM * DM / 4) / 256, 256>>>((const float4*)Wo, (float4*)wo, DM * DM / 4);

    dim3 g1(QKV_N / BN, ROWS / BM);
    gemm_tc<<<g1, 512, GEMM_SMEM_BYTES>>>(xr, wq, qkv, ROWS, QKV_N, DM);

    rope_kernel<<<ROWS, 256>>>(qkv, sinp, cosp);

    dim3 ga(SEQ / ATM, NH, BATCH);
    attn_tc<<<ga, 256, ATTN_SMEM_BYTES>>>(qkv, doc, att);

    dim3 g2(DM / BN, ROWS / BM);
    gemm_tc<<<g2, 512, GEMM_SMEM_BYTES>>>(att, wo, out, ROWS, DM, DM);
}